// round 11
// baseline (speedup 1.0000x reference)
#include <cuda_runtime.h>
#include <cuda_bf16.h>
#include <math.h>

// ---------------- problem constants ----------------
#define BSZ   8
#define MSEQ  1024
#define HDIM  1024
#define NHEAD 16
#define HDHD  64
#define HU    256
#define TOK   (BSZ*MSEQ)          // 8192
#define K3    3072                // 3*1024 interleaved split-K (projections)
#define NCH   48                  // K3/64 chunks

typedef unsigned long long ull;

__device__ __forceinline__ unsigned smem_u32(const void* p) {
    unsigned a;
    asm("{ .reg .u64 t; cvta.to.shared.u64 t, %1; cvt.u32.u64 %0, t; }" : "=r"(a) : "l"(p));
    return a;
}
__device__ __forceinline__ void ldmx4(unsigned* r, unsigned addr) {
    asm volatile("ldmatrix.sync.aligned.m8n8.x4.shared.b16 {%0,%1,%2,%3}, [%4];"
        : "=r"(r[0]), "=r"(r[1]), "=r"(r[2]), "=r"(r[3]) : "r"(addr));
}
__device__ __forceinline__ void mma16816(float* d, const unsigned* a, const unsigned* b) {
    asm volatile("mma.sync.aligned.m16n8k16.row.col.f32.bf16.bf16.f32 "
        "{%0,%1,%2,%3}, {%4,%5,%6,%7}, {%8,%9}, {%0,%1,%2,%3};"
        : "+f"(d[0]), "+f"(d[1]), "+f"(d[2]), "+f"(d[3])
        : "r"(a[0]), "r"(a[1]), "r"(a[2]), "r"(a[3]), "r"(b[0]), "r"(b[1]));
}
__device__ __forceinline__ unsigned sw128(unsigned off) {
    return off ^ ((off >> 3) & 0x70);
}
__device__ __forceinline__ unsigned short bf_split(float v, float &rem) {
    __nv_bfloat16 h = __float2bfloat16(v);
    rem = v - __bfloat162float(h);
    return *(unsigned short*)&h;
}

// ---------------- scratch ----------------
__device__ float g_V[TOK*HDIM];
__device__ float g_G[TOK*HDIM];
__device__ float g_H[TOK*HU];
__device__ float g_sigma[TOK];
__device__ float g_ctxp[BSZ*NHEAD*32*HDHD];
__device__ __nv_bfloat16 g_x3[(size_t)TOK*K3];             // (hi,hi,lo)
__device__ __nv_bfloat16 g_Wt3[(size_t)(4*1024+256)*K3];   // (hi,lo,hi)
__device__ __nv_bfloat16 g_Q3[(size_t)TOK*K3];             // Q split (hi,hi,lo), [tok][3*1024]
__device__ __nv_bfloat16 g_K3[(size_t)TOK*K3];             // K split (hi,lo,hi)
__device__ __nv_bfloat16 g_Vt3[(size_t)BSZ*NHEAD*64*K3];   // V^T split (hi,lo,hi), [bh][d][3n]

// =====================================================================
// Pre-pass 1: x -> x3 interleaved bf16 split (hi,hi,lo)
// =====================================================================
__global__ void split_x_kernel(const float* __restrict__ x)
{
    unsigned idx = blockIdx.x * 256 + threadIdx.x;
    size_t f0 = (size_t)idx * 8;
    unsigned row = (unsigned)(f0 >> 10), col = (unsigned)(f0 & 1023);
    float4 a = *(const float4*)(x + f0);
    float4 b = *(const float4*)(x + f0 + 4);
    union { __nv_bfloat16 h[24]; uint4 v[3]; } u;
    float e[8] = {a.x,a.y,a.z,a.w,b.x,b.y,b.z,b.w};
    #pragma unroll
    for (int i = 0; i < 8; i++) {
        __nv_bfloat16 hi = __float2bfloat16(e[i]);
        __nv_bfloat16 lo = __float2bfloat16(e[i] - __bfloat162float(hi));
        u.h[3*i] = hi; u.h[3*i+1] = hi; u.h[3*i+2] = lo;
    }
    __nv_bfloat16* out = g_x3 + (size_t)row * K3 + 3*col;
    uint4* o4 = (uint4*)out;
    o4[0] = u.v[0]; o4[1] = u.v[1]; o4[2] = u.v[2];
}

// =====================================================================
// Pre-pass 2: W[k][n] -> Wt3[n][3k] transposed split (hi,lo,hi)
// =====================================================================
__global__ void split_w_kernel(const float* __restrict__ Wq, const float* __restrict__ Wk,
                               const float* __restrict__ Wv, const float* __restrict__ Wg,
                               const float* __restrict__ Wu1)
{
    int which = blockIdx.z;
    const float* W; int NOUT;
    switch (which) {
        case 0: W = Wq;  NOUT = 1024; break;
        case 1: W = Wk;  NOUT = 1024; break;
        case 2: W = Wv;  NOUT = 1024; break;
        case 3: W = Wg;  NOUT = 1024; break;
        default:W = Wu1; NOUT = 256;  break;
    }
    int n0 = blockIdx.y * 32;
    if (n0 >= NOUT) return;
    int k0 = blockIdx.x * 64;
    int t = threadIdx.x;

    __shared__ float tile[64][33];
    int j = t & 31, ki0 = t >> 5;
    #pragma unroll
    for (int r = 0; r < 8; r++) {
        int k = ki0 + r*8;
        tile[k][j] = W[(size_t)(k0 + k) * NOUT + n0 + j];
    }
    __syncthreads();

    int n = t >> 3, kseg = t & 7;
    union { __nv_bfloat16 h[24]; uint4 v[3]; } u;
    #pragma unroll
    for (int e = 0; e < 8; e++) {
        float w = tile[kseg*8 + e][n];
        __nv_bfloat16 hi = __float2bfloat16(w);
        __nv_bfloat16 lo = __float2bfloat16(w - __bfloat162float(hi));
        u.h[3*e] = hi; u.h[3*e+1] = lo; u.h[3*e+2] = hi;
    }
    __nv_bfloat16* out = g_Wt3 + (size_t)which * 1024 * K3
                       + (size_t)(n0 + n) * K3 + 3*(k0 + kseg*8);
    uint4* o4 = (uint4*)out;
    o4[0] = u.v[0]; o4[1] = u.v[1]; o4[2] = u.v[2];
}

// =====================================================================
// Kernel 1: HMMA bf16 GEMM, block 128x128, K3=3072. Q/K written as split
// triples (bf16); V/G/H written fp32.
// =====================================================================
#define GSM_A0 0
#define GSM_A1 16384
#define GSM_B0 32768
#define GSM_B1 49152
#define GSM_TOTAL 65536

__global__ __launch_bounds__(256, 1)
void mma_gemm_kernel(const float* __restrict__ bq, const float* __restrict__ bk,
                     const float* __restrict__ bv, const float* __restrict__ bg,
                     const float* __restrict__ bu1)
{
    int which = blockIdx.z;
    const float* bias; float* out; int NOUT;
    switch (which) {
        case 0: bias = bq;  out = 0;   NOUT = 1024; break;
        case 1: bias = bk;  out = 0;   NOUT = 1024; break;
        case 2: bias = bv;  out = g_V; NOUT = 1024; break;
        case 3: bias = bg;  out = g_G; NOUT = 1024; break;
        default:bias = bu1; out = g_H; NOUT = 256;  break;
    }
    int n0 = blockIdx.x * 128;
    if (n0 >= NOUT) return;
    int m0 = blockIdx.y * 128;

    extern __shared__ char smem[];
    unsigned sbase = smem_u32(smem);
    int t = threadIdx.x, wid = t >> 5, lane = t & 31;
    int wm = wid & 3, wn = wid >> 2;

    int lrow = t >> 3, lseg = t & 7;
    const __nv_bfloat16* abase = g_x3 + (size_t)(m0 + lrow) * K3 + lseg*8;
    const __nv_bfloat16* bbase = g_Wt3 + (size_t)which * 1024 * K3
                               + (size_t)(n0 + lrow) * K3 + lseg*8;
    unsigned sts_off = sw128(lrow*128 + lseg*16);

    unsigned a_rb[2], a_xm[2];
    #pragma unroll
    for (int f = 0; f < 2; f++) {
        unsigned row = wm*32 + f*16 + (lane & 15);
        a_rb[f] = row * 128;
        a_xm[f] = (row & 7) << 4;
    }
    unsigned a_kh = (lane >> 4) * 16;
    unsigned b_rb[4], b_xm[4];
    #pragma unroll
    for (int p = 0; p < 4; p++) {
        unsigned row = wn*64 + p*16 + ((lane >> 4) << 3) + (lane & 7);
        b_rb[p] = row * 128;
        b_xm[p] = (row & 7) << 4;
    }
    unsigned b_kh = ((lane >> 3) & 1) * 16;

    float acc[2][8][4];
    #pragma unroll
    for (int f = 0; f < 2; f++)
        #pragma unroll
        for (int j = 0; j < 8; j++)
            #pragma unroll
            for (int q = 0; q < 4; q++) acc[f][j][q] = 0.0f;

    unsigned abuf[2] = {sbase + GSM_A0, sbase + GSM_A1};
    unsigned bbuf[2] = {sbase + GSM_B0, sbase + GSM_B1};

    uint4 av[4], bv4[4];
    #pragma unroll
    for (int i = 0; i < 4; i++) {
        av[i]  = *(const uint4*)(abase + (size_t)i*32*K3);
        bv4[i] = *(const uint4*)(bbase + (size_t)i*32*K3);
    }

    for (int c = 0; c < NCH; c++) {
        int buf = c & 1;
        #pragma unroll
        for (int i = 0; i < 4; i++) {
            *(uint4*)(smem + (buf ? GSM_A1 : GSM_A0) + i*4096 + sts_off) = av[i];
            *(uint4*)(smem + (buf ? GSM_B1 : GSM_B0) + i*4096 + sts_off) = bv4[i];
        }
        __syncthreads();

        if (c + 1 < NCH) {
            const __nv_bfloat16* ap = abase + (c+1)*64;
            const __nv_bfloat16* bp = bbase + (c+1)*64;
            #pragma unroll
            for (int i = 0; i < 4; i++) {
                av[i]  = *(const uint4*)(ap + (size_t)i*32*K3);
                bv4[i] = *(const uint4*)(bp + (size_t)i*32*K3);
            }
        }

        unsigned Ab = abuf[buf], Bb = bbuf[buf];
        #pragma unroll
        for (int kk = 0; kk < 4; kk++) {
            unsigned kb = kk * 32;
            unsigned afr[2][4];
            #pragma unroll
            for (int f = 0; f < 2; f++)
                ldmx4(afr[f], Ab + a_rb[f] + (((kb + a_kh) ^ a_xm[f])));
            #pragma unroll
            for (int p = 0; p < 4; p++) {
                unsigned bfr[4];
                ldmx4(bfr, Bb + b_rb[p] + (((kb + b_kh) ^ b_xm[p])));
                mma16816(acc[0][2*p],   afr[0], bfr);
                mma16816(acc[0][2*p+1], afr[0], bfr + 2);
                mma16816(acc[1][2*p],   afr[1], bfr);
                mma16816(acc[1][2*p+1], afr[1], bfr + 2);
            }
        }
        __syncthreads();
    }

    int mrow = lane >> 2;
    int ncol = (lane & 3) * 2;
    if (which <= 1) {
        // write split triples: Q=(hi,hi,lo), K=(hi,lo,hi)
        __nv_bfloat16* o3 = (which == 0) ? g_Q3 : g_K3;
        #pragma unroll
        for (int f = 0; f < 2; f++) {
            int mA = m0 + wm*32 + f*16 + mrow;
            #pragma unroll
            for (int j = 0; j < 8; j++) {
                int n = n0 + wn*64 + j*8 + ncol;
                float bb0 = bias[n], bb1 = bias[n+1];
                #pragma unroll
                for (int half = 0; half < 2; half++) {
                    float v0 = acc[f][j][2*half]   + bb0;
                    float v1 = acc[f][j][2*half+1] + bb1;
                    float r0, r1;
                    unsigned short h0 = bf_split(v0, r0);
                    unsigned short h1 = bf_split(v1, r1);
                    __nv_bfloat16 l0b = __float2bfloat16(r0);
                    __nv_bfloat16 l1b = __float2bfloat16(r1);
                    unsigned short l0 = *(unsigned short*)&l0b;
                    unsigned short l1 = *(unsigned short*)&l1b;
                    unsigned u0, u1, u2;
                    if (which == 0) {   // (h0,h0,l0),(h1,h1,l1)
                        u0 = (unsigned)h0 | ((unsigned)h0 << 16);
                        u1 = (unsigned)l0 | ((unsigned)h1 << 16);
                        u2 = (unsigned)h1 | ((unsigned)l1 << 16);
                    } else {            // (h0,l0,h0),(h1,l1,h1)
                        u0 = (unsigned)h0 | ((unsigned)l0 << 16);
                        u1 = (unsigned)h0 | ((unsigned)h1 << 16);
                        u2 = (unsigned)l1 | ((unsigned)h1 << 16);
                    }
                    unsigned* dst = (unsigned*)(o3 + (size_t)(mA + half*8) * K3 + 3*n);
                    dst[0] = u0; dst[1] = u1; dst[2] = u2;
                }
            }
        }
    } else {
        #pragma unroll
        for (int f = 0; f < 2; f++) {
            int mA = m0 + wm*32 + f*16 + mrow;
            #pragma unroll
            for (int j = 0; j < 8; j++) {
                int n = n0 + wn*64 + j*8 + ncol;
                float bb0 = bias[n], bb1 = bias[n+1];
                float v0 = acc[f][j][0] + bb0, v1 = acc[f][j][1] + bb1;
                float v2 = acc[f][j][2] + bb0, v3 = acc[f][j][3] + bb1;
                if (which == 3) {
                    v0 = 1.0f/(1.0f+expf(-v0)); v1 = 1.0f/(1.0f+expf(-v1));
                    v2 = 1.0f/(1.0f+expf(-v2)); v3 = 1.0f/(1.0f+expf(-v3));
                } else if (which == 4) {
                    v0 = fmaxf(v0,0.f); v1 = fmaxf(v1,0.f);
                    v2 = fmaxf(v2,0.f); v3 = fmaxf(v3,0.f);
                }
                *(float2*)(out + (size_t)mA * NOUT + n)     = make_float2(v0, v1);
                *(float2*)(out + (size_t)(mA+8) * NOUT + n) = make_float2(v2, v3);
            }
        }
    }
}

// =====================================================================
// Pre-pass 3: V -> Vt3[bh][d][3n] transposed split (hi,lo,hi)
// grid (8 ntiles, 16 h, 8 b), 256 thr
// =====================================================================
__global__ void vt3_kernel()
{
    __shared__ float tile[128][65];
    int nt = blockIdx.x, h = blockIdx.y, b = blockIdx.z;
    int n0 = nt * 128;
    int t = threadIdx.x;

    for (int i = t; i < 2048; i += 256) {
        int r = i >> 4, c4 = (i & 15) * 4;
        float4 v = *(const float4*)(g_V + (size_t)(b*1024 + n0 + r)*1024 + h*64 + c4);
        tile[r][c4] = v.x; tile[r][c4+1] = v.y; tile[r][c4+2] = v.z; tile[r][c4+3] = v.w;
    }
    __syncthreads();

    int d = t >> 2, seg = t & 3;
    __nv_bfloat16* obase = g_Vt3 + ((size_t)(b*NHEAD + h)*64 + d) * K3 + (size_t)3*(n0 + seg*32);
    #pragma unroll
    for (int grp = 0; grp < 4; grp++) {
        union { __nv_bfloat16 hh[24]; uint4 v[3]; } u;
        #pragma unroll
        for (int e = 0; e < 8; e++) {
            float w = tile[seg*32 + grp*8 + e][d];
            __nv_bfloat16 hi = __float2bfloat16(w);
            __nv_bfloat16 lo = __float2bfloat16(w - __bfloat162float(hi));
            u.hh[3*e] = hi; u.hh[3*e+1] = lo; u.hh[3*e+2] = hi;
        }
        uint4* o4 = (uint4*)(obase + grp*24);
        o4[0] = u.v[0]; o4[1] = u.v[1]; o4[2] = u.v[2];
    }
}

// =====================================================================
// Kernel 2: sigma
// =====================================================================
__global__ void sigma_finish_kernel(const float* __restrict__ Wu2,
                                    const float* __restrict__ bu2,
                                    float* __restrict__ out_sigma)
{
    int w = threadIdx.x >> 5, lane = threadIdx.x & 31;
    int row = blockIdx.x * 8 + w;
    const float* hr = g_H + (size_t)row * HU;
    float s = 0.0f;
    #pragma unroll
    for (int c = 0; c < 8; c++) {
        int j = lane + (c << 5);
        s = fmaf(hr[j], Wu2[j], s);
    }
    #pragma unroll
    for (int o = 16; o > 0; o >>= 1) s += __shfl_xor_sync(0xffffffffu, s, o);
    if (lane == 0) {
        float u  = s + bu2[0];
        float sp = fmaxf(u, 0.0f) + log1pf(expf(-fabsf(u))) + 1e-6f;
        g_sigma[row]   = sp;
        out_sigma[row] = sp;
    }
}

// =====================================================================
// Kernel 3: attention, HMMA scores + HMMA PV.
// Block = (32-row mtile, head, batch), 256 threads (8 warps).
// smem layout (bytes):
//   S    [32][1024] f32 : 0      .. 131072
//   Q3s  [32][400B]     : 131072 .. 143872   (192 bf16 + pad)
//   CH region (75264B)  : 143872 .. 219136
//      scores: K3s [128][400B]
//      PV:     Vt3s[64][784B] + P3s[32][784B] (at +50176)
//      final:  ctx [32][64] f32 (8192) + red 1024
//   rs   [1024] f32     : 219136 .. 223232
// =====================================================================
#define AS_S    0
#define AS_Q3   131072
#define AS_CH   143872
#define AS_P3   (AS_CH + 50176)
#define AS_CTX  AS_CH
#define AS_RED  (AS_CH + 8192)
#define AS_RS   219136
#define AS_TOTAL 223232

__global__ __launch_bounds__(256, 1)
void attn_kernel(float* __restrict__ attn_out)
{
    extern __shared__ char smc[];
    float* S  = (float*)(smc + AS_S);
    float* rs = (float*)(smc + AS_RS);
    unsigned sbase = smem_u32(smc);

    int mt = blockIdx.x, h = blockIdx.y, b = blockIdx.z;
    int m0 = mt * 32;
    int t  = threadIdx.x, wid = t >> 5, lane = t & 31;

    for (int i = t; i < 1024; i += 256) rs[i] = 1.0f / g_sigma[b*1024 + i];

    {   // Q3 tile: rows 32, 384B each, padded stride 400
        int row = t >> 3, seg = t & 7;
        const __nv_bfloat16* src = g_Q3 + (size_t)(b*1024 + m0 + row)*K3 + h*192 + seg*24;
        uint4 v0 = *(const uint4*)(src);
        uint4 v1 = *(const uint4*)(src + 8);
        uint4 v2 = *(const uint4*)(src + 16);
        char* dst = smc + AS_Q3 + row*400 + seg*48;
        *(uint4*)(dst) = v0; *(uint4*)(dst+16) = v1; *(uint4*)(dst+32) = v2;
    }

    // ---- scores: 8 chunks of 128 keys, HMMA K3H=192 ----
    unsigned a_kh = (lane >> 4) * 16;
    unsigned b_kh = ((lane >> 3) & 1) * 16;
    unsigned qrow[2];
    #pragma unroll
    for (int f = 0; f < 2; f++) qrow[f] = (f*16 + (lane & 15)) * 400;
    unsigned krow = (wid*16 + ((lane >> 4) << 3) + (lane & 7)) * 400;

    for (int nt = 0; nt < 8; nt++) {
        int n0 = nt << 7;
        __syncthreads();
        {   // K3s chunk: 128 rows x 384B
            int row = t >> 1, half = t & 1;
            const __nv_bfloat16* src = g_K3 + (size_t)(b*1024 + n0 + row)*K3 + h*192 + half*96;
            char* dst = smc + AS_CH + row*400 + half*192;
            #pragma unroll
            for (int i = 0; i < 12; i++)
                *(uint4*)(dst + i*16) = *(const uint4*)(src + i*8);
        }
        __syncthreads();

        float acc[2][2][4];
        #pragma unroll
        for (int f = 0; f < 2; f++)
            #pragma unroll
            for (int j = 0; j < 2; j++)
                #pragma unroll
                for (int q = 0; q < 4; q++) acc[f][j][q] = 0.0f;

        #pragma unroll
        for (int ks = 0; ks < 12; ks++) {
            unsigned kb = ks * 32;
            unsigned afr[2][4], bfr[4];
            ldmx4(afr[0], sbase + AS_Q3 + qrow[0] + kb + a_kh);
            ldmx4(afr[1], sbase + AS_Q3 + qrow[1] + kb + a_kh);
            ldmx4(bfr,    sbase + AS_CH + krow    + kb + b_kh);
            mma16816(acc[0][0], afr[0], bfr);
            mma16816(acc[0][1], afr[0], bfr + 2);
            mma16816(acc[1][0], afr[1], bfr);
            mma16816(acc[1][1], afr[1], bfr + 2);
        }

        #pragma unroll
        for (int f = 0; f < 2; f++) {
            int row = f*16 + (lane >> 2);
            #pragma unroll
            for (int j = 0; j < 2; j++) {
                int col = wid*16 + j*8 + (lane & 3)*2;
                float fm0 = 0.125f * rs[m0 + row];
                float fm8 = 0.125f * rs[m0 + row + 8];
                float rn0 = rs[n0 + col], rn1 = rs[n0 + col + 1];
                *(float2*)&S[row*1024 + n0 + col] =
                    make_float2(acc[f][j][0]*fm0*rn0, acc[f][j][1]*fm0*rn1);
                *(float2*)&S[(row+8)*1024 + n0 + col] =
                    make_float2(acc[f][j][2]*fm8*rn0, acc[f][j][3]*fm8*rn1);
            }
        }
    }
    __syncthreads();

    // ---- softmax per row; write attn; keep P in S ----
    {
        float* ab = attn_out + ((size_t)((b*NHEAD + h)*1024 + m0))*1024;
        for (int r = 0; r < 4; r++) {
            int m = (wid << 2) + r;
            float* Sr = S + m*1024;
            float mx = -1e30f;
            #pragma unroll
            for (int c = 0; c < 32; c++) mx = fmaxf(mx, Sr[lane + (c<<5)]);
            #pragma unroll
            for (int o = 16; o > 0; o >>= 1) mx = fmaxf(mx, __shfl_xor_sync(0xffffffffu, mx, o));
            float vals[32];
            float sum = 0.0f;
            #pragma unroll
            for (int c = 0; c < 32; c++) {
                float e = exp2f((Sr[lane + (c<<5)] - mx) * 1.4426950408889634f);
                vals[c] = e; sum += e;
            }
            #pragma unroll
            for (int o = 16; o > 0; o >>= 1) sum += __shfl_xor_sync(0xffffffffu, sum, o);
            float inv = 1.0f / sum;
            float* gr = ab + (size_t)m * 1024;
            #pragma unroll
            for (int c = 0; c < 32; c++) {
                float p = vals[c] * inv;
                Sr[lane + (c<<5)] = p;
                gr[lane + (c<<5)] = p;
            }
        }
    }

    // ---- PV: HMMA, 8 chunks of 128 keys, k3=384 per chunk ----
    int wm2 = wid & 1, wd = wid >> 1;
    unsigned prow = (wm2*16 + (lane & 15)) * 784;
    unsigned vrow = (wd*16 + ((lane >> 4) << 3) + (lane & 7)) * 784;

    float apv[2][4];
    #pragma unroll
    for (int j = 0; j < 2; j++)
        #pragma unroll
        for (int q = 0; q < 4; q++) apv[j][q] = 0.0f;

    for (int nt = 0; nt < 8; nt++) {
        int n0 = nt << 7;
        __syncthreads();
        {   // P3s: split P chunk to (hi,hi,lo) triples
            int m = t >> 3, nseg = t & 7;
            const float* Sr = S + m*1024 + n0 + nseg*16;
            char* dst = smc + AS_P3 + m*784 + nseg*96;
            #pragma unroll
            for (int i = 0; i < 16; i++) {
                float p = Sr[i];
                float rem;
                unsigned short hi = bf_split(p, rem);
                __nv_bfloat16 lob = __float2bfloat16(rem);
                unsigned short lo = *(unsigned short*)&lob;
                *(unsigned short*)(dst + i*6)     = hi;
                *(unsigned short*)(dst + i*6 + 2) = hi;
                *(unsigned short*)(dst + i*6 + 4) = lo;
            }
        }
        {   // Vt3s chunk: 64 rows x 768B
            int row = t >> 2, q = t & 3;
            const __nv_bfloat16* src = g_Vt3 + ((size_t)(b*NHEAD + h)*64 + row)*K3
                                     + nt*384 + q*96;
            char* dst = smc + AS_CH + row*784 + q*192;
            #pragma unroll
            for (int i = 0; i < 12; i++)
                *(uint4*)(dst + i*16) = *(const uint4*)(src + i*8);
        }
        __syncthreads();

        #pragma unroll
        for (int ks = 0; ks < 24; ks++) {
            unsigned kb = ks * 32;
            unsigned afr[4], bfr[4];
            ldmx4(afr, sbase + AS_P3 + prow + kb + a_kh);
            ldmx4(bfr, sbase + AS_CH + vrow + kb + b_kh);
            mma16816(apv[0], afr, bfr);
            mma16816(apv[1], afr, bfr + 2);
        }
    }
    __syncthreads();

    {   // store ctx frags
        float* ctx = (float*)(smc + AS_CTX);
        int row = wm2*16 + (lane >> 2);
        #pragma unroll
        for (int j = 0; j < 2; j++) {
            int col = wd*16 + j*8 + (lane & 3)*2;
            *(float2*)&ctx[row*64 + col]     = make_float2(apv[j][0], apv[j][1]);
            *(float2*)&ctx[(row+8)*64 + col] = make_float2(apv[j][2], apv[j][3]);
        }
    }
    __syncthreads();
    {   // gate + reduce over m
        float* ctx = (float*)(smc + AS_CTX);
        float* red = (float*)(smc + AS_RED);
        int d = t & 63, mg = t >> 6;
        float part = 0.0f;
        #pragma unroll
        for (int i = 0; i < 8; i++) {
            int m = mg*8 + i;
            float gv = g_G[((size_t)(b*1024 + m0 + m))*1024 + h*64 + d];
            part = fmaf(ctx[m*64 + d], gv, part);
        }
        red[t] = part;
        __syncthreads();
        if (t < 64) {
            float s = red[t] + red[64 + t] + red[128 + t] + red[192 + t];
            g_ctxp[(((size_t)(b*NHEAD + h))*32 + mt)*64 + t] = s;
        }
    }
}

// =====================================================================
// Kernel 4: z = mean_m(fused) @ Wo + bo
// =====================================================================
__global__ void z_kernel(const float* __restrict__ Wo, const float* __restrict__ bo,
                         float* __restrict__ z)
{
    __shared__ float mf[1024];
    __shared__ float red[256];
    int b = blockIdx.x, cb = blockIdx.y, t = threadIdx.x;
    for (int j = t; j < 1024; j += 256) {
        const float* p = g_ctxp + ((size_t)(b*NHEAD + (j >> 6)))*32*64 + (j & 63);
        float s = 0.0f;
        #pragma unroll
        for (int mtl = 0; mtl < 32; mtl++) s += p[mtl*64];
        mf[j] = s * (1.0f/1024.0f);
    }
    __syncthreads();
    int c = cb*64 + (t & 63);
    int kq = t >> 6;
    float a0 = 0.f, a1 = 0.f, a2 = 0.f, a3 = 0.f;
    int jb = kq * 256;
    #pragma unroll 4
    for (int jj = 0; jj < 256; jj += 4) {
        a0 = fmaf(mf[jb+jj  ], Wo[(jb+jj  )*1024 + c], a0);
        a1 = fmaf(mf[jb+jj+1], Wo[(jb+jj+1)*1024 + c], a1);
        a2 = fmaf(mf[jb+jj+2], Wo[(jb+jj+2)*1024 + c], a2);
        a3 = fmaf(mf[jb+jj+3], Wo[(jb+jj+3)*1024 + c], a3);
    }
    red[t] = (a0 + a1) + (a2 + a3);
    __syncthreads();
    if (t < 64)
        z[(size_t)b*1024 + c] = red[t] + red[64+t] + red[128+t] + red[192+t] + bo[c];
}

// =====================================================================
// launch
// =====================================================================
extern "C" void kernel_launch(void* const* d_in, const int* in_sizes, int n_in,
                              void* d_out, int out_size)
{
    const float* x   = (const float*)d_in[0];
    const float* Wq  = (const float*)d_in[1];  const float* bq  = (const float*)d_in[2];
    const float* Wk  = (const float*)d_in[3];  const float* bk  = (const float*)d_in[4];
    const float* Wv  = (const float*)d_in[5];  const float* bv  = (const float*)d_in[6];
    const float* Wg  = (const float*)d_in[7];  const float* bg  = (const float*)d_in[8];
    const float* Wo  = (const float*)d_in[9];  const float* bo  = (const float*)d_in[10];
    const float* Wu1 = (const float*)d_in[11]; const float* bu1 = (const float*)d_in[12];
    const float* Wu2 = (const float*)d_in[13]; const float* bu2 = (const float*)d_in[14];

    float* out       = (float*)d_out;
    float* z_out     = out;
    float* attn_out  = out + 8192;
    float* sigma_out = out + 8192 + (size_t)BSZ*NHEAD*MSEQ*MSEQ;

    cudaFuncSetAttribute(attn_kernel, cudaFuncAttributeMaxDynamicSharedMemorySize, AS_TOTAL);
    cudaFuncSetAttribute(mma_gemm_kernel, cudaFuncAttributeMaxDynamicSharedMemorySize, GSM_TOTAL);

    split_x_kernel<<<4096, 256>>>(x);
    split_w_kernel<<<dim3(16, 32, 5), 256>>>(Wq, Wk, Wv, Wg, Wu1);
    mma_gemm_kernel<<<dim3(8, 64, 5), 256, GSM_TOTAL>>>(bq, bk, bv, bg, bu1);
    vt3_kernel<<<dim3(8, NHEAD, BSZ), 256>>>();
    sigma_finish_kernel<<<TOK / 8, 256>>>(Wu2, bu2, sigma_out);
    attn_kernel<<<dim3(32, NHEAD, BSZ), 256, AS_TOTAL>>>(attn_out);
    z_kernel<<<dim3(BSZ, 16), 256>>>(Wo, bo, z_out);
}

// round 12
// speedup vs baseline: 1.1122x; 1.1122x over previous
#include <cuda_runtime.h>
#include <cuda_bf16.h>
#include <math.h>

// ---------------- problem constants ----------------
#define BSZ   8
#define MSEQ  1024
#define HDIM  1024
#define NHEAD 16
#define HDHD  64
#define HU    256
#define TOK   (BSZ*MSEQ)          // 8192
#define K3    3072                // 3*1024 interleaved split-K
#define NCH   48                  // K3/64 chunks

typedef unsigned long long ull;

// ---- packed fp32x2 helpers (attention kernel) ----
__device__ __forceinline__ void ffma2(ull &d, ull a, ull b) {
    asm("fma.rn.f32x2 %0, %1, %2, %0;" : "+l"(d) : "l"(a), "l"(b));
}
__device__ __forceinline__ ull fdup(float x) {
    ull r; unsigned u = __float_as_uint(x);
    asm("mov.b64 %0, {%1, %1};" : "=l"(r) : "r"(u)); return r;
}
__device__ __forceinline__ float2 funpack(ull v) {
    unsigned lo, hi;
    asm("mov.b64 {%0, %1}, %2;" : "=r"(lo), "=r"(hi) : "l"(v));
    return make_float2(__uint_as_float(lo), __uint_as_float(hi));
}

__device__ __forceinline__ unsigned smem_u32(const void* p) {
    unsigned a;
    asm("{ .reg .u64 t; cvta.to.shared.u64 t, %1; cvt.u32.u64 %0, t; }" : "=r"(a) : "l"(p));
    return a;
}
__device__ __forceinline__ void ldmx4(unsigned* r, unsigned addr) {
    asm volatile("ldmatrix.sync.aligned.m8n8.x4.shared.b16 {%0,%1,%2,%3}, [%4];"
        : "=r"(r[0]), "=r"(r[1]), "=r"(r[2]), "=r"(r[3]) : "r"(addr));
}
__device__ __forceinline__ void mma16816(float* d, const unsigned* a, const unsigned* b) {
    asm volatile("mma.sync.aligned.m16n8k16.row.col.f32.bf16.bf16.f32 "
        "{%0,%1,%2,%3}, {%4,%5,%6,%7}, {%8,%9}, {%0,%1,%2,%3};"
        : "+f"(d[0]), "+f"(d[1]), "+f"(d[2]), "+f"(d[3])
        : "r"(a[0]), "r"(a[1]), "r"(a[2]), "r"(a[3]), "r"(b[0]), "r"(b[1]));
}
__device__ __forceinline__ unsigned sw128(unsigned off) {
    return off ^ ((off >> 3) & 0x70);
}

// ---------------- scratch ----------------
__device__ float g_Q[TOK*HDIM];
__device__ float g_K[TOK*HDIM];
__device__ float g_V[TOK*HDIM];
__device__ float g_G[TOK*HDIM];
__device__ float g_H[TOK*HU];
__device__ float g_sigma[TOK];
__device__ float g_ctxp[BSZ*NHEAD*32*HDHD];
__device__ __nv_bfloat16 g_x3[(size_t)TOK*K3];             // (hi,hi,lo)
__device__ __nv_bfloat16 g_Wt3[(size_t)(4*1024+256)*K3];   // (hi,lo,hi)

// =====================================================================
// Pre-pass (merged): y==0 -> split x; y==1 -> split+transpose W
// =====================================================================
__global__ void prepass_kernel(const float* __restrict__ x,
                               const float* __restrict__ Wq, const float* __restrict__ Wk,
                               const float* __restrict__ Wv, const float* __restrict__ Wg,
                               const float* __restrict__ Wu1)
{
    int t = threadIdx.x;
    if (blockIdx.y == 0) {
        // ---- split_x: x -> (hi,hi,lo) ----
        unsigned idx = blockIdx.x * 256 + t;
        size_t f0 = (size_t)idx * 8;
        unsigned row = (unsigned)(f0 >> 10), col = (unsigned)(f0 & 1023);
        float4 a = *(const float4*)(x + f0);
        float4 b = *(const float4*)(x + f0 + 4);
        union { __nv_bfloat16 h[24]; uint4 v[3]; } u;
        float e[8] = {a.x,a.y,a.z,a.w,b.x,b.y,b.z,b.w};
        #pragma unroll
        for (int i = 0; i < 8; i++) {
            __nv_bfloat16 hi = __float2bfloat16(e[i]);
            __nv_bfloat16 lo = __float2bfloat16(e[i] - __bfloat162float(hi));
            u.h[3*i] = hi; u.h[3*i+1] = hi; u.h[3*i+2] = lo;
        }
        __nv_bfloat16* out = g_x3 + (size_t)row * K3 + 3*col;
        uint4* o4 = (uint4*)out;
        o4[0] = u.v[0]; o4[1] = u.v[1]; o4[2] = u.v[2];
        return;
    }
    // ---- split_w: W[k][n] -> Wt3[n][3k] (hi,lo,hi) ----
    unsigned bx = blockIdx.x;
    if (bx >= 2560) return;
    int which = bx / 512;
    int rem = bx % 512;
    int k0 = (rem & 15) * 64;
    int nt = rem >> 4;
    const float* W; int NOUT;
    switch (which) {
        case 0: W = Wq;  NOUT = 1024; break;
        case 1: W = Wk;  NOUT = 1024; break;
        case 2: W = Wv;  NOUT = 1024; break;
        case 3: W = Wg;  NOUT = 1024; break;
        default:W = Wu1; NOUT = 256;  break;
    }
    int n0 = nt * 32;
    if (n0 >= NOUT) return;

    __shared__ float tile[64][33];
    int j = t & 31, ki0 = t >> 5;
    #pragma unroll
    for (int r = 0; r < 8; r++) {
        int k = ki0 + r*8;
        tile[k][j] = W[(size_t)(k0 + k) * NOUT + n0 + j];
    }
    __syncthreads();

    int n = t >> 3, kseg = t & 7;
    union { __nv_bfloat16 h[24]; uint4 v[3]; } u;
    #pragma unroll
    for (int e = 0; e < 8; e++) {
        float w = tile[kseg*8 + e][n];
        __nv_bfloat16 hi = __float2bfloat16(w);
        __nv_bfloat16 lo = __float2bfloat16(w - __bfloat162float(hi));
        u.h[3*e] = hi; u.h[3*e+1] = lo; u.h[3*e+2] = hi;
    }
    __nv_bfloat16* out = g_Wt3 + (size_t)which * 1024 * K3
                       + (size_t)(n0 + n) * K3 + 3*(k0 + kseg*8);
    uint4* o4 = (uint4*)out;
    o4[0] = u.v[0]; o4[1] = u.v[1]; o4[2] = u.v[2];
}

// =====================================================================
// Kernel 1: HMMA bf16 GEMM (mma.sync m16n8k16), block 128x128, K3=3072
// =====================================================================
#define GSM_A0 0
#define GSM_A1 16384
#define GSM_B0 32768
#define GSM_B1 49152
#define GSM_TOTAL 65536

__global__ __launch_bounds__(256, 1)
void mma_gemm_kernel(const float* __restrict__ bq, const float* __restrict__ bk,
                     const float* __restrict__ bv, const float* __restrict__ bg,
                     const float* __restrict__ bu1)
{
    int which = blockIdx.z;
    const float* bias; float* out; int NOUT;
    switch (which) {
        case 0: bias = bq;  out = g_Q; NOUT = 1024; break;
        case 1: bias = bk;  out = g_K; NOUT = 1024; break;
        case 2: bias = bv;  out = g_V; NOUT = 1024; break;
        case 3: bias = bg;  out = g_G; NOUT = 1024; break;
        default:bias = bu1; out = g_H; NOUT = 256;  break;
    }
    int n0 = blockIdx.x * 128;
    if (n0 >= NOUT) return;
    int m0 = blockIdx.y * 128;

    extern __shared__ char smem[];
    unsigned sbase = smem_u32(smem);
    int t = threadIdx.x, wid = t >> 5, lane = t & 31;
    int wm = wid & 3, wn = wid >> 2;

    int lrow = t >> 3, lseg = t & 7;
    const __nv_bfloat16* abase = g_x3 + (size_t)(m0 + lrow) * K3 + lseg*8;
    const __nv_bfloat16* bbase = g_Wt3 + (size_t)which * 1024 * K3
                               + (size_t)(n0 + lrow) * K3 + lseg*8;
    unsigned sts_off = sw128(lrow*128 + lseg*16);

    unsigned a_rb[2], a_xm[2];
    #pragma unroll
    for (int f = 0; f < 2; f++) {
        unsigned row = wm*32 + f*16 + (lane & 15);
        a_rb[f] = row * 128;
        a_xm[f] = (row & 7) << 4;
    }
    unsigned a_kh = (lane >> 4) * 16;
    unsigned b_rb[4], b_xm[4];
    #pragma unroll
    for (int p = 0; p < 4; p++) {
        unsigned row = wn*64 + p*16 + ((lane >> 4) << 3) + (lane & 7);
        b_rb[p] = row * 128;
        b_xm[p] = (row & 7) << 4;
    }
    unsigned b_kh = ((lane >> 3) & 1) * 16;

    float acc[2][8][4];
    #pragma unroll
    for (int f = 0; f < 2; f++)
        #pragma unroll
        for (int j = 0; j < 8; j++)
            #pragma unroll
            for (int q = 0; q < 4; q++) acc[f][j][q] = 0.0f;

    unsigned abuf[2] = {sbase + GSM_A0, sbase + GSM_A1};
    unsigned bbuf[2] = {sbase + GSM_B0, sbase + GSM_B1};

    uint4 av[4], bv4[4];
    #pragma unroll
    for (int i = 0; i < 4; i++) {
        av[i]  = *(const uint4*)(abase + (size_t)i*32*K3);
        bv4[i] = *(const uint4*)(bbase + (size_t)i*32*K3);
    }

    for (int c = 0; c < NCH; c++) {
        int buf = c & 1;
        #pragma unroll
        for (int i = 0; i < 4; i++) {
            *(uint4*)(smem + (buf ? GSM_A1 : GSM_A0) + i*4096 + sts_off) = av[i];
            *(uint4*)(smem + (buf ? GSM_B1 : GSM_B0) + i*4096 + sts_off) = bv4[i];
        }
        __syncthreads();

        if (c + 1 < NCH) {
            const __nv_bfloat16* ap = abase + (c+1)*64;
            const __nv_bfloat16* bp = bbase + (c+1)*64;
            #pragma unroll
            for (int i = 0; i < 4; i++) {
                av[i]  = *(const uint4*)(ap + (size_t)i*32*K3);
                bv4[i] = *(const uint4*)(bp + (size_t)i*32*K3);
            }
        }

        unsigned Ab = abuf[buf], Bb = bbuf[buf];
        #pragma unroll
        for (int kk = 0; kk < 4; kk++) {
            unsigned kb = kk * 32;
            unsigned afr[2][4];
            #pragma unroll
            for (int f = 0; f < 2; f++)
                ldmx4(afr[f], Ab + a_rb[f] + (((kb + a_kh) ^ a_xm[f])));
            #pragma unroll
            for (int p = 0; p < 4; p++) {
                unsigned bfr[4];
                ldmx4(bfr, Bb + b_rb[p] + (((kb + b_kh) ^ b_xm[p])));
                mma16816(acc[0][2*p],   afr[0], bfr);
                mma16816(acc[0][2*p+1], afr[0], bfr + 2);
                mma16816(acc[1][2*p],   afr[1], bfr);
                mma16816(acc[1][2*p+1], afr[1], bfr + 2);
            }
        }
        __syncthreads();
    }

    int mrow = lane >> 2;
    int ncol = (lane & 3) * 2;
    #pragma unroll
    for (int f = 0; f < 2; f++) {
        int mA = m0 + wm*32 + f*16 + mrow;
        #pragma unroll
        for (int j = 0; j < 8; j++) {
            int n = n0 + wn*64 + j*8 + ncol;
            float bb0 = bias[n], bb1 = bias[n+1];
            float v0 = acc[f][j][0] + bb0, v1 = acc[f][j][1] + bb1;
            float v2 = acc[f][j][2] + bb0, v3 = acc[f][j][3] + bb1;
            if (which == 3) {
                v0 = 1.0f/(1.0f+expf(-v0)); v1 = 1.0f/(1.0f+expf(-v1));
                v2 = 1.0f/(1.0f+expf(-v2)); v3 = 1.0f/(1.0f+expf(-v3));
            } else if (which == 4) {
                v0 = fmaxf(v0,0.f); v1 = fmaxf(v1,0.f);
                v2 = fmaxf(v2,0.f); v3 = fmaxf(v3,0.f);
            }
            *(float2*)(out + (size_t)mA * NOUT + n)     = make_float2(v0, v1);
            *(float2*)(out + (size_t)(mA+8) * NOUT + n) = make_float2(v2, v3);
        }
    }
}

// =====================================================================
// Kernel 2: sigma = softplus(H @ Wu2 + bu2) + 1e-6
// =====================================================================
__global__ void sigma_finish_kernel(const float* __restrict__ Wu2,
                                    const float* __restrict__ bu2,
                                    float* __restrict__ out_sigma)
{
    int w = threadIdx.x >> 5, lane = threadIdx.x & 31;
    int row = blockIdx.x * 8 + w;
    const float* hr = g_H + (size_t)row * HU;
    float s = 0.0f;
    #pragma unroll
    for (int c = 0; c < 8; c++) {
        int j = lane + (c << 5);
        s = fmaf(hr[j], Wu2[j], s);
    }
    #pragma unroll
    for (int o = 16; o > 0; o >>= 1) s += __shfl_xor_sync(0xffffffffu, s, o);
    if (lane == 0) {
        float u  = s + bu2[0];
        float sp = fmaxf(u, 0.0f) + log1pf(expf(-fabsf(u))) + 1e-6f;
        g_sigma[row]   = sp;
        out_sigma[row] = sp;
    }
}

// =====================================================================
// Kernel 3: attention (R8/R10-passing FFMA2 version) — 4th launch => profiled
// =====================================================================
#define ATTN_SMEM_FLOATS (32*1024 + 64*32 + 16384 + 1024 + 256)

__global__ __launch_bounds__(256, 1)
void attn_kernel(float* __restrict__ attn_out)
{
    extern __shared__ float sm[];
    float* S   = sm;
    float* Qs  = S   + 32*1024;
    float* KV  = Qs  + 64*32;
    float* rs  = KV  + 16384;
    float* red = rs  + 1024;

    int mt = blockIdx.x, h = blockIdx.y, b = blockIdx.z;
    int m0 = mt * 32;
    int t  = threadIdx.x;

    for (int i = t; i < 1024; i += 256) rs[i] = 1.0f / g_sigma[b*1024 + i];

    {
        int m = t >> 3, part = t & 7;
        const float* qp = g_Q + ((size_t)(b*1024 + m0 + m))*1024 + h*64 + part*8;
        float4 q0 = *(const float4*)qp;
        float4 q1 = *(const float4*)(qp + 4);
        int k = part*8;
        Qs[(k+0)*32+m]=q0.x; Qs[(k+1)*32+m]=q0.y; Qs[(k+2)*32+m]=q0.z; Qs[(k+3)*32+m]=q0.w;
        Qs[(k+4)*32+m]=q1.x; Qs[(k+5)*32+m]=q1.y; Qs[(k+6)*32+m]=q1.z; Qs[(k+7)*32+m]=q1.w;
    }

    int tm4 = (t >> 5) << 2;
    int tn8 = (t & 31) << 3;
    for (int nt = 0; nt < 4; nt++) {
        int n0 = nt << 8;
        __syncthreads();
        #pragma unroll
        for (int p = 0; p < 2; p++) {
            int n = p*128 + (t >> 1), half = t & 1;
            const float* kp = g_K + ((size_t)(b*1024 + n0 + n))*1024 + h*64 + half*32;
            #pragma unroll
            for (int i = 0; i < 8; i++) {
                float4 kv = *(const float4*)(kp + i*4);
                int kk = half*32 + i*4;
                KV[(kk+0)*256+n]=kv.x; KV[(kk+1)*256+n]=kv.y;
                KV[(kk+2)*256+n]=kv.z; KV[(kk+3)*256+n]=kv.w;
            }
        }
        __syncthreads();

        ull acc[4][4];
        #pragma unroll
        for (int i = 0; i < 4; i++)
            #pragma unroll
            for (int j = 0; j < 4; j++) acc[i][j] = 0ull;

        #pragma unroll 8
        for (int k = 0; k < 64; k++) {
            float4 av = *(const float4*)&Qs[k*32 + tm4];
            const ulonglong2* bp = (const ulonglong2*)&KV[k*256 + tn8];
            ulonglong2 B0 = bp[0], B1 = bp[1];
            ull bn[4] = {B0.x, B0.y, B1.x, B1.y};
            ull am[4] = {fdup(av.x), fdup(av.y), fdup(av.z), fdup(av.w)};
            #pragma unroll
            for (int i = 0; i < 4; i++)
                #pragma unroll
                for (int j = 0; j < 4; j++)
                    ffma2(acc[i][j], am[i], bn[j]);
        }
        #pragma unroll
        for (int i = 0; i < 4; i++) {
            int m = tm4 + i;
            float fm = 0.125f * rs[m0 + m];
            float o[8];
            #pragma unroll
            for (int j = 0; j < 4; j++) {
                float2 p = funpack(acc[i][j]);
                o[2*j]   = p.x * fm * rs[n0 + tn8 + 2*j];
                o[2*j+1] = p.y * fm * rs[n0 + tn8 + 2*j + 1];
            }
            *(float4*)&S[m*1024 + n0 + tn8]     = make_float4(o[0],o[1],o[2],o[3]);
            *(float4*)&S[m*1024 + n0 + tn8 + 4] = make_float4(o[4],o[5],o[6],o[7]);
        }
    }
    __syncthreads();

    {
        int w = t >> 5, lane = t & 31;
        float* ab = attn_out + ((size_t)((b*NHEAD + h)*1024 + m0))*1024;
        for (int r = 0; r < 4; r++) {
            int m = (w << 2) + r;
            float* Sr = S + m*1024;
            float mx = -1e30f;
            #pragma unroll
            for (int c = 0; c < 32; c++) mx = fmaxf(mx, Sr[lane + (c<<5)]);
            #pragma unroll
            for (int o = 16; o > 0; o >>= 1) mx = fmaxf(mx, __shfl_xor_sync(0xffffffffu, mx, o));
            float vals[32];
            float sum = 0.0f;
            #pragma unroll
            for (int c = 0; c < 32; c++) {
                float e = exp2f((Sr[lane + (c<<5)] - mx) * 1.4426950408889634f);
                vals[c] = e; sum += e;
            }
            #pragma unroll
            for (int o = 16; o > 0; o >>= 1) sum += __shfl_xor_sync(0xffffffffu, sum, o);
            float inv = 1.0f / sum;
            float* gr = ab + (size_t)m * 1024;
            #pragma unroll
            for (int c = 0; c < 32; c++) {
                float p = vals[c] * inv;
                Sr[lane + (c<<5)] = p;
                gr[lane + (c<<5)] = p;
            }
        }
    }
    __syncthreads();

    int sub = t >> 6;
    int u   = t & 63;
    int dp4 = (u & 15) << 2;
    int mg8 = (u >> 4) << 3;
    ull acc2[8][2];
    #pragma unroll
    for (int i = 0; i < 8; i++) { acc2[i][0] = 0ull; acc2[i][1] = 0ull; }

    int vn = t & 127, vhalf = t >> 7;
    const float* vbase = g_V + ((size_t)(b*1024 + vn))*1024 + h*64 + vhalf*32;
    float4 vreg[8];
    #pragma unroll
    for (int i = 0; i < 8; i++) vreg[i] = *(const float4*)(vbase + i*4);

    for (int nt = 0; nt < 8; nt++) {
        int n0 = nt << 7;
        __syncthreads();
        {
            float* dst = KV + vn*68 + vhalf*32;
            #pragma unroll
            for (int i = 0; i < 8; i++) *(float4*)&dst[i*4] = vreg[i];
        }
        __syncthreads();
        if (nt < 7) {
            vbase += (size_t)128 * 1024;
            #pragma unroll
            for (int i = 0; i < 8; i++) vreg[i] = *(const float4*)(vbase + i*4);
        }

        #pragma unroll 4
        for (int nn = 0; nn < 32; nn++) {
            int n = sub*32 + nn;
            const ulonglong2* vp = (const ulonglong2*)&KV[n*68 + dp4];
            ulonglong2 V0 = vp[0];
            #pragma unroll
            for (int i = 0; i < 8; i++) {
                ull sd = fdup(S[(mg8 + i)*1024 + n0 + n]);
                ffma2(acc2[i][0], sd, V0.x);
                ffma2(acc2[i][1], sd, V0.y);
            }
        }
    }
    __syncthreads();

    {
        float* scr = S;
        #pragma unroll
        for (int i = 0; i < 8; i++) {
            float2 p0 = funpack(acc2[i][0]);
            float2 p1 = funpack(acc2[i][1]);
            *(float4*)&scr[sub*2048 + (mg8 + i)*64 + dp4] = make_float4(p0.x, p0.y, p1.x, p1.y);
        }
    }
    __syncthreads();
    {
        float* scr = S;
        int d = t & 63, mgr = t >> 6;
        float part = 0.0f;
        #pragma unroll
        for (int i = 0; i < 8; i++) {
            int m = mgr*8 + i;
            float c = scr[m*64 + d] + scr[2048 + m*64 + d]
                    + scr[4096 + m*64 + d] + scr[6144 + m*64 + d];
            float gv = g_G[((size_t)(b*1024 + m0 + m))*1024 + h*64 + d];
            part = fmaf(c, gv, part);
        }
        red[t] = part;
    }
    __syncthreads();
    if (t < 64) {
        float s = red[t] + red[64 + t] + red[128 + t] + red[192 + t];
        g_ctxp[(((size_t)(b*NHEAD + h))*32 + mt)*64 + t] = s;
    }
}

// =====================================================================
// Kernel 4: z = mean_m(fused) @ Wo + bo   (grid 8x16, 256 thr, k-split 4)
// =====================================================================
__global__ void z_kernel(const float* __restrict__ Wo, const float* __restrict__ bo,
                         float* __restrict__ z)
{
    __shared__ float mf[1024];
    __shared__ float red[256];
    int b = blockIdx.x, cb = blockIdx.y, t = threadIdx.x;
    for (int j = t; j < 1024; j += 256) {
        const float* p = g_ctxp + ((size_t)(b*NHEAD + (j >> 6)))*32*64 + (j & 63);
        float s = 0.0f;
        #pragma unroll
        for (int mtl = 0; mtl < 32; mtl++) s += p[mtl*64];
        mf[j] = s * (1.0f/1024.0f);
    }
    __syncthreads();
    int c = cb*64 + (t & 63);
    int kq = t >> 6;
    float a0 = 0.f, a1 = 0.f, a2 = 0.f, a3 = 0.f;
    int jb = kq * 256;
    #pragma unroll 4
    for (int jj = 0; jj < 256; jj += 4) {
        a0 = fmaf(mf[jb+jj  ], Wo[(jb+jj  )*1024 + c], a0);
        a1 = fmaf(mf[jb+jj+1], Wo[(jb+jj+1)*1024 + c], a1);
        a2 = fmaf(mf[jb+jj+2], Wo[(jb+jj+2)*1024 + c], a2);
        a3 = fmaf(mf[jb+jj+3], Wo[(jb+jj+3)*1024 + c], a3);
    }
    red[t] = (a0 + a1) + (a2 + a3);
    __syncthreads();
    if (t < 64)
        z[(size_t)b*1024 + c] = red[t] + red[64+t] + red[128+t] + red[192+t] + bo[c];
}

// =====================================================================
// launch — attention is the 4th launch (profiled by the -s5-c1 capture)
// =====================================================================
extern "C" void kernel_launch(void* const* d_in, const int* in_sizes, int n_in,
                              void* d_out, int out_size)
{
    const float* x   = (const float*)d_in[0];
    const float* Wq  = (const float*)d_in[1];  const float* bq  = (const float*)d_in[2];
    const float* Wk  = (const float*)d_in[3];  const float* bk  = (const float*)d_in[4];
    const float* Wv  = (const float*)d_in[5];  const float* bv  = (const float*)d_in[6];
    const float* Wg  = (const float*)d_in[7];  const float* bg  = (const float*)d_in[8];
    const float* Wo  = (const float*)d_in[9];  const float* bo  = (const float*)d_in[10];
    const float* Wu1 = (const float*)d_in[11]; const float* bu1 = (const float*)d_in[12];
    const float* Wu2 = (const float*)d_in[13]; const float* bu2 = (const float*)d_in[14];

    float* out       = (float*)d_out;
    float* z_out     = out;
    float* attn_out  = out + 8192;
    float* sigma_out = out + 8192 + (size_t)BSZ*NHEAD*MSEQ*MSEQ;

    cudaFuncSetAttribute(attn_kernel, cudaFuncAttributeMaxDynamicSharedMemorySize,
                         ATTN_SMEM_FLOATS * (int)sizeof(float));
    cudaFuncSetAttribute(mma_gemm_kernel, cudaFuncAttributeMaxDynamicSharedMemorySize, GSM_TOTAL);

    prepass_kernel<<<dim3(4096, 2), 256>>>(x, Wq, Wk, Wv, Wg, Wu1);                  // 1
    mma_gemm_kernel<<<dim3(8, 64, 5), 256, GSM_TOTAL>>>(bq, bk, bv, bg, bu1);        // 2
    sigma_finish_kernel<<<TOK / 8, 256>>>(Wu2, bu2, sigma_out);                      // 3
    attn_kernel<<<dim3(32, NHEAD, BSZ), 256,                                         // 4 (profiled)
                  ATTN_SMEM_FLOATS * (int)sizeof(float)>>>(attn_out);
    z_kernel<<<dim3(BSZ, 16), 256>>>(Wo, bo, z_out);                                 // 5
}